// round 9
// baseline (speedup 1.0000x reference)
#include <cuda_runtime.h>
#include <cuda_fp16.h>
#include <cstdint>

// Problem-size caps (fixed by the dataset)
#define MAXN 100000
#define MAXE 1600000
#define DFEAT 48
#define NH2   24          // half2 per node row
#define KITER 10
#define ALPHA 0.1f
#define NBIN  256         // degree bins for balance sort

// ---------------- scratch (static device memory; no allocations) -------------
__device__ int     g_is64;
__device__ int     g_deg[MAXN];
__device__ int     g_ndeg[MAXN];
__device__ int     g_off[MAXN + 1];
__device__ int     g_bsums[256];
__device__ int     g_row[MAXE];
__device__ int     g_col[MAXE];
__device__ int     g_slot[MAXE];
__device__ int2    g_edge[MAXE];                    // (newcol, raw-w bits), sorted
__device__ int     g_dhist[NBIN];
__device__ int     g_dpos[NBIN];
__device__ int     g_perm[MAXN];                    // newid -> orig
__device__ int     g_iperm[MAXN];                   // orig -> newid
__device__ __half2 g_xhp[(size_t)MAXN * NH2];       // x fp16, permuted layout
__device__ float2  g_xp[(size_t)MAXN * NH2];        // x fp32, permuted layout
__device__ __half2 g_hh0[(size_t)MAXN * NH2];       // ping (permuted layout)
__device__ __half2 g_hh1[(size_t)MAXN * NH2];       // pong (permuted layout)

// ---------------- precompute kernels ----------------------------------------

// Detect int64 vs int32 edge_index: int64 (values < 2^31) has every odd 32-bit
// word zero; int32 data has random indices there.
__global__ void k_detect(const int* __restrict__ ei32, int E) {
    __shared__ int any;
    if (threadIdx.x == 0) any = 0;
    __syncthreads();
    int nchk = 1024; if (nchk > E) nchk = E;
    for (int i = threadIdx.x; i < nchk; i += blockDim.x)
        if (ei32[2 * i + 1] != 0) any = 1;
    __syncthreads();
    if (threadIdx.x == 0) g_is64 = (any == 0) ? 1 : 0;
}

__global__ void k_zero(int* deg, int* dhist, int* dpos, int n) {
    int i = blockIdx.x * blockDim.x + threadIdx.x;
    if (i < n) deg[i] = 0;
    if (i < NBIN) { dhist[i] = 0; dpos[i] = 0; }
}

// Narrow indices (dual dtype); degree count; record per-row slot per edge.
__global__ void k_narrow(const void* __restrict__ ei,
                         int* __restrict__ deg,
                         int* __restrict__ row32, int* __restrict__ col32,
                         int* __restrict__ slot, int E, int N) {
    int e = blockIdx.x * blockDim.x + threadIdx.x;
    if (e >= E) return;
    int r, c;
    if (g_is64) {
        const long long* p = (const long long*)ei;
        r = (int)p[e];
        c = (int)p[(size_t)E + e];
    } else {
        const int* p = (const int*)ei;
        r = p[e];
        c = p[E + e];
    }
    if (r < 0) r = 0; if (r >= N) r = N - 1;   // crash-proofing only
    if (c < 0) c = 0; if (c >= N) c = N - 1;
    row32[e] = r;
    col32[e] = c;
    slot[e] = atomicAdd(&deg[r], 1);
}

// Degree histogram over nodes (binned, clamped)
__global__ void k_dhist(const int* __restrict__ deg, int* __restrict__ dhist, int n) {
    int i = blockIdx.x * blockDim.x + threadIdx.x;
    if (i >= n) return;
    int d = deg[i]; if (d > NBIN - 1) d = NBIN - 1;
    atomicAdd(&dhist[d], 1);
}

// Exclusive scan of the 256-bin histogram (single block)
__global__ void k_dscan(int* __restrict__ dhist) {
    __shared__ int sh[NBIN];
    int v = dhist[threadIdx.x];
    sh[threadIdx.x] = v;
    __syncthreads();
    for (int d = 1; d < NBIN; d <<= 1) {
        int t = 0;
        if (threadIdx.x >= d) t = sh[threadIdx.x - d];
        __syncthreads();
        if (threadIdx.x >= d) sh[threadIdx.x] += t;
        __syncthreads();
    }
    dhist[threadIdx.x] = sh[threadIdx.x] - v;   // exclusive
}

// Build perm (newid->orig) and iperm (orig->newid); gather new-space degrees.
__global__ void k_dperm(const int* __restrict__ deg, const int* __restrict__ dhist,
                        int* __restrict__ dpos, int* __restrict__ perm,
                        int* __restrict__ iperm, int n) {
    int i = blockIdx.x * blockDim.x + threadIdx.x;
    if (i >= n) return;
    int d = deg[i]; if (d > NBIN - 1) d = NBIN - 1;
    int p = dhist[d] + atomicAdd(&dpos[d], 1);
    perm[p] = i;
    iperm[i] = p;
}

__global__ void k_ndeg(const int* __restrict__ deg, const int* __restrict__ perm,
                       int* __restrict__ ndeg, int n) {
    int i = blockIdx.x * blockDim.x + threadIdx.x;
    if (i < n) ndeg[i] = deg[perm[i]];
}

// 3-phase exclusive scan of ndeg -> off (new-ID space)
__global__ void k_scan1(const int* __restrict__ deg, int* __restrict__ off,
                        int* __restrict__ bsums, int n) {
    __shared__ int sh[1024];
    int i = blockIdx.x * 1024 + threadIdx.x;
    int v = (i < n) ? deg[i] : 0;
    sh[threadIdx.x] = v;
    __syncthreads();
    for (int d = 1; d < 1024; d <<= 1) {
        int t = 0;
        if (threadIdx.x >= d) t = sh[threadIdx.x - d];
        __syncthreads();
        if (threadIdx.x >= d) sh[threadIdx.x] += t;
        __syncthreads();
    }
    if (i < n) off[i] = sh[threadIdx.x] - v;
    if (threadIdx.x == 1023) bsums[blockIdx.x] = sh[1023];
}

__global__ void k_scan2(int* bsums, int nb) {
    if (threadIdx.x == 0 && blockIdx.x == 0) {
        int acc = 0;
        for (int i = 0; i < nb; i++) { int t = bsums[i]; bsums[i] = acc; acc += t; }
    }
}

__global__ void k_scan3(int* __restrict__ off, const int* __restrict__ bsums,
                        int n, int total) {
    int i = blockIdx.x * 1024 + threadIdx.x;
    if (i < n) off[i] += bsums[blockIdx.x];
    if (i == 0) off[n] = total;
}

// Scatter edges into new-ID CSR using precomputed slots; relabel col via iperm.
__global__ void k_scatter(const int* __restrict__ row32, const int* __restrict__ col32,
                          const int* __restrict__ slot,
                          const float* __restrict__ w,
                          const int* __restrict__ off, const int* __restrict__ iperm,
                          int2* __restrict__ ed, int E) {
    int e = blockIdx.x * blockDim.x + threadIdx.x;
    if (e >= E) return;
    int nr = iperm[row32[e]];
    int nc = iperm[col32[e]];
    int p = off[nr] + slot[e];
    ed[p] = make_int2(nc, __float_as_int(w[e]));
}

// Copy x into permuted fp16 + fp32 layouts. i indexes new layout.
__global__ void k_xperm(const float2* __restrict__ x2, const int* __restrict__ perm,
                        __half2* __restrict__ xhp, float2* __restrict__ xp, int n) {
    int i = blockIdx.x * blockDim.x + threadIdx.x;   // over N*NH2
    if (i >= n * NH2) return;
    int nid = i / NH2, j = i - nid * NH2;
    float2 v = __ldg(&x2[perm[nid] * NH2 + j]);
    xhp[i] = __float22half2_rn(v);
    xp[i]  = v;
}

// ---------------- propagation mainloop ---------------------------------------
// Nodes relabeled degree-sorted: iteration space == memory space, coalesced.
// 8 lanes per node; lane l owns half2 chunks {l, l+8, l+16}.
// Normalization folded into epilogue: 0.9/(sum_w + 1e-10).
template<bool FINAL>
__global__ void __launch_bounds__(256)
k_proph(const __half2* __restrict__ hin,
        const __half2* __restrict__ xhp, const float2* __restrict__ xp,
        __half2* __restrict__ hout, float2* __restrict__ fout,
        const int* __restrict__ off, const int2* __restrict__ ed,
        const int* __restrict__ perm, int n) {
    int gid  = blockIdx.x * blockDim.x + threadIdx.x;
    int node = gid >> 3;
    int lane = gid & 7;
    if (node >= n) return;

    int s = __ldg(&off[node]);
    int e = __ldg(&off[node + 1]);

    float a0x = 0.f, a0y = 0.f, a1x = 0.f, a1y = 0.f, a2x = 0.f, a2y = 0.f;
    float ws = 0.f;
    for (int idx = s; idx < e; idx++) {
        int2 t = __ldg(&ed[idx]);                       // broadcast in 8-lane group
        float ww = __int_as_float(t.y);
        ws += ww;
        const __half2* hp = hin + t.x * NH2 + lane;
        float2 v0 = __half22float2(__ldg(hp));
        float2 v1 = __half22float2(__ldg(hp + 8));
        float2 v2 = __half22float2(__ldg(hp + 16));
        a0x = fmaf(ww, v0.x, a0x);  a0y = fmaf(ww, v0.y, a0y);
        a1x = fmaf(ww, v1.x, a1x);  a1y = fmaf(ww, v1.y, a1y);
        a2x = fmaf(ww, v2.x, a2x);  a2y = fmaf(ww, v2.y, a2y);
    }

    float sc = (1.0f - ALPHA) / (ws + 1e-10f);

    int o = node * NH2 + lane;
    float2 xv0, xv1, xv2;
    if (FINAL) {
        xv0 = __ldg(xp + o); xv1 = __ldg(xp + o + 8); xv2 = __ldg(xp + o + 16);
    } else {
        xv0 = __half22float2(__ldg(xhp + o));
        xv1 = __half22float2(__ldg(xhp + o + 8));
        xv2 = __half22float2(__ldg(xhp + o + 16));
    }
    float2 r0 = make_float2(fmaf(sc, a0x, ALPHA * xv0.x), fmaf(sc, a0y, ALPHA * xv0.y));
    float2 r1 = make_float2(fmaf(sc, a1x, ALPHA * xv1.x), fmaf(sc, a1y, ALPHA * xv1.y));
    float2 r2 = make_float2(fmaf(sc, a2x, ALPHA * xv2.x), fmaf(sc, a2y, ALPHA * xv2.y));

    if (FINAL) {
        // write back to ORIGINAL node position (64B-chunk scatter, once)
        int oo = __ldg(&perm[node]) * NH2 + lane;
        fout[oo] = r0; fout[oo + 8] = r1; fout[oo + 16] = r2;
    } else {
        hout[o]      = __float22half2_rn(r0);
        hout[o + 8]  = __float22half2_rn(r1);
        hout[o + 16] = __float22half2_rn(r2);
    }
}

// ---------------- launcher ----------------------------------------------------
extern "C" void kernel_launch(void* const* d_in, const int* in_sizes, int n_in,
                              void* d_out, int out_size) {
    const float* x  = (const float*)d_in[0];
    const void*  ei = d_in[1];
    const float* ew = (const float*)d_in[2];

    int N = in_sizes[0] / DFEAT;
    int E = in_sizes[2];
    if (N > MAXN) N = MAXN;
    if (E > MAXE) E = MAXE;

    int *deg, *ndeg, *off, *bsums, *row32, *col32, *slot, *dhist, *dpos, *perm, *iperm;
    int2 *edge; __half2 *xhp, *hh0, *hh1; float2 *xp;
    cudaGetSymbolAddress((void**)&deg,   g_deg);
    cudaGetSymbolAddress((void**)&ndeg,  g_ndeg);
    cudaGetSymbolAddress((void**)&off,   g_off);
    cudaGetSymbolAddress((void**)&bsums, g_bsums);
    cudaGetSymbolAddress((void**)&row32, g_row);
    cudaGetSymbolAddress((void**)&col32, g_col);
    cudaGetSymbolAddress((void**)&slot,  g_slot);
    cudaGetSymbolAddress((void**)&dhist, g_dhist);
    cudaGetSymbolAddress((void**)&dpos,  g_dpos);
    cudaGetSymbolAddress((void**)&perm,  g_perm);
    cudaGetSymbolAddress((void**)&iperm, g_iperm);
    cudaGetSymbolAddress((void**)&edge,  g_edge);
    cudaGetSymbolAddress((void**)&xhp,   g_xhp);
    cudaGetSymbolAddress((void**)&xp,    g_xp);
    cudaGetSymbolAddress((void**)&hh0,   g_hh0);
    cudaGetSymbolAddress((void**)&hh1,   g_hh1);

    const float2* x2 = (const float2*)x;
    int nb  = (N + 1023) / 1024;
    int nh2 = N * NH2;

    k_detect<<<1, 256>>>((const int*)ei, E);
    k_zero<<<(N + 255) / 256, 256>>>(deg, dhist, dpos, N);
    k_narrow<<<(E + 255) / 256, 256>>>(ei, deg, row32, col32, slot, E, N);
    k_dhist<<<(N + 255) / 256, 256>>>(deg, dhist, N);
    k_dscan<<<1, NBIN>>>(dhist);
    k_dperm<<<(N + 255) / 256, 256>>>(deg, dhist, dpos, perm, iperm, N);
    k_ndeg<<<(N + 255) / 256, 256>>>(deg, perm, ndeg, N);
    k_scan1<<<nb, 1024>>>(ndeg, off, bsums, N);
    k_scan2<<<1, 32>>>(bsums, nb);
    k_scan3<<<nb, 1024>>>(off, bsums, N, E);
    k_scatter<<<(E + 255) / 256, 256>>>(row32, col32, slot, ew, off, iperm, edge, E);
    k_xperm<<<(nh2 + 255) / 256, 256>>>(x2, perm, xhp, xp, N);

    int pblocks = (N * 8 + 255) / 256;
    const __half2* src = xhp;
    for (int k = 0; k < KITER; k++) {
        if (k == KITER - 1) {
            k_proph<true><<<pblocks, 256>>>(src, xhp, xp, nullptr, (float2*)d_out,
                                            off, edge, perm, N);
        } else {
            __half2* dst = ((k & 1) == 0) ? hh0 : hh1;
            k_proph<false><<<pblocks, 256>>>(src, xhp, xp, dst, nullptr,
                                             off, edge, perm, N);
            src = dst;
        }
    }
}

// round 12
// speedup vs baseline: 1.2273x; 1.2273x over previous
#include <cuda_runtime.h>
#include <cuda_fp16.h>
#include <cstdint>

// Problem-size caps (fixed by the dataset)
#define MAXN 100000
#define MAXE 1600000
#define DFEAT 48
#define NH2   24          // half2 per node row
#define KITER 10
#define ALPHA 0.1f

// ---------------- scratch (static device memory; no allocations) -------------
__device__ int     g_is64;
__device__ int     g_deg[MAXN];
__device__ int     g_off[MAXN + 1];
__device__ int     g_bsums[256];
__device__ int     g_slot[MAXE];
__device__ int2    g_edge[MAXE];                    // (col, raw-w bits), row-sorted
__device__ __half2 g_xh[(size_t)MAXN * NH2];        // x in fp16
__device__ __half2 g_hh0[(size_t)MAXN * NH2];       // ping
__device__ __half2 g_hh1[(size_t)MAXN * NH2];       // pong

// ---------------- precompute kernels ----------------------------------------

// Detect int64 vs int32 edge_index: int64 (values < 2^31) has every odd 32-bit
// word zero; int32 data has random indices there.
__global__ void k_detect(const int* __restrict__ ei32, int E) {
    __shared__ int any;
    if (threadIdx.x == 0) any = 0;
    __syncthreads();
    int nchk = 1024; if (nchk > E) nchk = E;
    for (int i = threadIdx.x; i < nchk; i += blockDim.x)
        if (ei32[2 * i + 1] != 0) any = 1;
    __syncthreads();
    if (threadIdx.x == 0) g_is64 = (any == 0) ? 1 : 0;
}

__global__ void k_zero(int* deg, int n) {
    int i = blockIdx.x * blockDim.x + threadIdx.x;
    if (i < n) deg[i] = 0;
}

// x (fp32) -> half2
__global__ void k_xhalf(const float2* __restrict__ x2, __half2* __restrict__ xh, int n2) {
    int i = blockIdx.x * blockDim.x + threadIdx.x;
    if (i < n2) xh[i] = __float22half2_rn(x2[i]);
}

// Degree count + per-row slot per edge. 4 edges/thread, vector index loads
// for MLP (DRAM first-touch latency hiding).
__global__ void k_narrow(const void* __restrict__ ei,
                         int* __restrict__ deg, int* __restrict__ slot,
                         int E, int N) {
    int base = (blockIdx.x * blockDim.x + threadIdx.x) * 4;
    if (base >= E) return;
    int r[4];
    if (g_is64) {
        const longlong2* p = (const longlong2*)ei;   // rows start at element 0
        longlong2 a = __ldg(&p[(base >> 1)]);
        longlong2 b = __ldg(&p[(base >> 1) + 1]);
        r[0] = (int)a.x; r[1] = (int)a.y; r[2] = (int)b.x; r[3] = (int)b.y;
    } else {
        const int4* p = (const int4*)ei;
        int4 a = __ldg(&p[base >> 2]);
        r[0] = a.x; r[1] = a.y; r[2] = a.z; r[3] = a.w;
    }
#pragma unroll
    for (int j = 0; j < 4; j++) {
        int e = base + j;
        if (e >= E) break;
        int rr = r[j];
        if (rr < 0) rr = 0; if (rr >= N) rr = N - 1;   // crash-proofing only
        slot[e] = atomicAdd(&deg[rr], 1);
    }
}

// 3-phase exclusive scan of deg -> off
__global__ void k_scan1(const int* __restrict__ deg, int* __restrict__ off,
                        int* __restrict__ bsums, int n) {
    __shared__ int sh[1024];
    int i = blockIdx.x * 1024 + threadIdx.x;
    int v = (i < n) ? deg[i] : 0;
    sh[threadIdx.x] = v;
    __syncthreads();
    for (int d = 1; d < 1024; d <<= 1) {
        int t = 0;
        if (threadIdx.x >= d) t = sh[threadIdx.x - d];
        __syncthreads();
        if (threadIdx.x >= d) sh[threadIdx.x] += t;
        __syncthreads();
    }
    if (i < n) off[i] = sh[threadIdx.x] - v;
    if (threadIdx.x == 1023) bsums[blockIdx.x] = sh[1023];
}

__global__ void k_scan2(int* bsums, int nb) {
    if (threadIdx.x == 0 && blockIdx.x == 0) {
        int acc = 0;
        for (int i = 0; i < nb; i++) { int t = bsums[i]; bsums[i] = acc; acc += t; }
    }
}

__global__ void k_scan3(int* __restrict__ off, const int* __restrict__ bsums,
                        int n, int total) {
    int i = blockIdx.x * 1024 + threadIdx.x;
    if (i < n) off[i] += bsums[blockIdx.x];
    if (i == 0) off[n] = total;
}

// Counting-sort scatter using precomputed slots (no atomics): (col, raw w).
// Re-narrows indices from ei (L2-hot after k_narrow).
__global__ void k_scatter(const void* __restrict__ ei,
                          const int* __restrict__ slot,
                          const float* __restrict__ w,
                          const int* __restrict__ off, int2* __restrict__ ed,
                          int E, int N) {
    int e = blockIdx.x * blockDim.x + threadIdx.x;
    if (e >= E) return;
    int r, c;
    if (g_is64) {
        const long long* p = (const long long*)ei;
        r = (int)p[e];
        c = (int)p[(size_t)E + e];
    } else {
        const int* p = (const int*)ei;
        r = p[e];
        c = p[E + e];
    }
    if (r < 0) r = 0; if (r >= N) r = N - 1;
    if (c < 0) c = 0; if (c >= N) c = N - 1;
    int p2 = off[r] + slot[e];
    ed[p2] = make_int2(c, __float_as_int(w[e]));
}

// ---------------- propagation mainloop ---------------------------------------
// 8 lanes per destination node; lane l owns half2 chunks {l, l+8, l+16}.
// Normalization folded into epilogue: 0.9/(sum_w + 1e-10).
template<bool FINAL>
__global__ void __launch_bounds__(256)
k_proph(const __half2* __restrict__ hin,
        const __half2* __restrict__ xh, const float2* __restrict__ x2,
        __half2* __restrict__ hout, float2* __restrict__ fout,
        const int* __restrict__ off, const int2* __restrict__ ed, int n) {
    int gid  = blockIdx.x * blockDim.x + threadIdx.x;
    int node = gid >> 3;
    int lane = gid & 7;
    if (node >= n) return;

    int s = __ldg(&off[node]);
    int e = __ldg(&off[node + 1]);

    float a0x = 0.f, a0y = 0.f, a1x = 0.f, a1y = 0.f, a2x = 0.f, a2y = 0.f;
    float ws = 0.f;
    for (int idx = s; idx < e; idx++) {
        int2 t = __ldg(&ed[idx]);                       // broadcast in 8-lane group
        float ww = __int_as_float(t.y);
        ws += ww;
        const __half2* hp = hin + t.x * NH2 + lane;
        float2 v0 = __half22float2(__ldg(hp));
        float2 v1 = __half22float2(__ldg(hp + 8));
        float2 v2 = __half22float2(__ldg(hp + 16));
        a0x = fmaf(ww, v0.x, a0x);  a0y = fmaf(ww, v0.y, a0y);
        a1x = fmaf(ww, v1.x, a1x);  a1y = fmaf(ww, v1.y, a1y);
        a2x = fmaf(ww, v2.x, a2x);  a2y = fmaf(ww, v2.y, a2y);
    }

    float sc = (1.0f - ALPHA) / (ws + 1e-10f);

    int o = node * NH2 + lane;
    float2 xv0, xv1, xv2;
    if (FINAL) {
        xv0 = __ldg(x2 + o); xv1 = __ldg(x2 + o + 8); xv2 = __ldg(x2 + o + 16);
    } else {
        xv0 = __half22float2(__ldg(xh + o));
        xv1 = __half22float2(__ldg(xh + o + 8));
        xv2 = __half22float2(__ldg(xh + o + 16));
    }
    float2 r0 = make_float2(fmaf(sc, a0x, ALPHA * xv0.x), fmaf(sc, a0y, ALPHA * xv0.y));
    float2 r1 = make_float2(fmaf(sc, a1x, ALPHA * xv1.x), fmaf(sc, a1y, ALPHA * xv1.y));
    float2 r2 = make_float2(fmaf(sc, a2x, ALPHA * xv2.x), fmaf(sc, a2y, ALPHA * xv2.y));

    if (FINAL) {
        fout[o] = r0; fout[o + 8] = r1; fout[o + 16] = r2;
    } else {
        hout[o]      = __float22half2_rn(r0);
        hout[o + 8]  = __float22half2_rn(r1);
        hout[o + 16] = __float22half2_rn(r2);
    }
}

// ---------------- launcher ----------------------------------------------------
extern "C" void kernel_launch(void* const* d_in, const int* in_sizes, int n_in,
                              void* d_out, int out_size) {
    const float* x  = (const float*)d_in[0];
    const void*  ei = d_in[1];
    const float* ew = (const float*)d_in[2];

    int N = in_sizes[0] / DFEAT;
    int E = in_sizes[2];
    if (N > MAXN) N = MAXN;
    if (E > MAXE) E = MAXE;

    int *deg, *off, *bsums, *slot;
    int2 *edge; __half2 *xh, *hh0, *hh1;
    cudaGetSymbolAddress((void**)&deg,   g_deg);
    cudaGetSymbolAddress((void**)&off,   g_off);
    cudaGetSymbolAddress((void**)&bsums, g_bsums);
    cudaGetSymbolAddress((void**)&slot,  g_slot);
    cudaGetSymbolAddress((void**)&edge,  g_edge);
    cudaGetSymbolAddress((void**)&xh,    g_xh);
    cudaGetSymbolAddress((void**)&hh0,   g_hh0);
    cudaGetSymbolAddress((void**)&hh1,   g_hh1);

    const float2* x2 = (const float2*)x;
    int nb  = (N + 1023) / 1024;
    int nh2 = N * NH2;

    k_detect<<<1, 256>>>((const int*)ei, E);
    k_zero<<<(N + 255) / 256, 256>>>(deg, N);
    k_xhalf<<<(nh2 + 255) / 256, 256>>>(x2, xh, nh2);
    k_narrow<<<((E + 3) / 4 + 255) / 256, 256>>>(ei, deg, slot, E, N);
    k_scan1<<<nb, 1024>>>(deg, off, bsums, N);
    k_scan2<<<1, 32>>>(bsums, nb);
    k_scan3<<<nb, 1024>>>(off, bsums, N, E);
    k_scatter<<<(E + 255) / 256, 256>>>(ei, slot, ew, off, edge, E, N);

    int pblocks = (N * 8 + 255) / 256;
    const __half2* src = xh;
    for (int k = 0; k < KITER; k++) {
        if (k == KITER - 1) {
            k_proph<true><<<pblocks, 256>>>(src, xh, x2, nullptr, (float2*)d_out,
                                            off, edge, N);
        } else {
            __half2* dst = ((k & 1) == 0) ? hh0 : hh1;
            k_proph<false><<<pblocks, 256>>>(src, xh, x2, dst, nullptr,
                                             off, edge, N);
            src = dst;
        }
    }
}